// round 9
// baseline (speedup 1.0000x reference)
#include <cuda_runtime.h>
#include <math.h>

#define B_  8
#define C_  12
#define S_  784
#define NTOK 785
#define D_  768
#define HH  28
#define PATCH 84
#define GCNH 512

#define ROWF4    192u          /* 768 floats per row */
#define BATF4    150720u       /* 785*192 per batch  */
#define NHS4     1205760u      /* 8*785*192          */
#define NCHUNK   1176u         /* (8*784*192)/1024   */
#define CH_P1    776u          /* chunks copied in phase 1 */

// ---------------- scratch (no allocation allowed) ----------------
__device__ float         g_amap[B_*C_*S_];
__device__ unsigned char g_selflag[B_*C_*S_];
__device__ float         g_struct[B_*D_];
__device__ float         g_wk[B_*GCNH];
__device__ int           g_pidx[B_*S_];
__device__ int           g_key[B_*S_];

// ---------------- software grid barrier ----------------
__device__ unsigned g_gen = 0;
__device__ unsigned g_cnt = 0;

__device__ __forceinline__ void gridSync(unsigned nblk) {
    __syncthreads();
    if (threadIdx.x == 0) {
        volatile unsigned* vgen = &g_gen;
        unsigned my_gen = *vgen;                 // read gen BEFORE arriving
        __threadfence();                         // release prior writes
        if (atomicAdd(&g_cnt, 1u) == nblk - 1u) {
            g_cnt = 0;                           // only releaser touches it here
            __threadfence();
            *vgen = my_gen + 1u;                 // release
        } else {
            while (*vgen == my_gen) { __nanosleep(64); }
        }
        __threadfence();                         // acquire
    }
    __syncthreads();
}

// monotone float->uint: a > b <=> f2u(a) > f2u(b)
__device__ __forceinline__ unsigned f2u(float f) {
    unsigned u = __float_as_uint(f);
    return (u & 0x80000000u) ? ~u : (u | 0x80000000u);
}

// ---------------- shared memory union ----------------
struct SmemSel {
    float    sc[S_];
    unsigned key[S_];
    int      hist[256];
    int      wtot[8];
    unsigned prefix;
    int      k;
};
struct SmemKB {
    float    pw[S_];
    float    binm[S_];
    float    cnt[S_];
    float    wsum[8];
    unsigned long long wkey[8];
    float4   wq[8];
    float    mean, panchor;
    float4   q;
    int      anchor;
};
struct SmemMV { float wk[GCNH]; float partr[256]; };
struct SmemRk { int kk[S_]; };
union SmemAll { SmemSel sel; SmemKB kb; SmemMV mv; SmemRk rk; };

// ---- bulk copy of rows 1..784 (chunk = 1024 float4, ILP=4) ------------------
__device__ __forceinline__ void copyChunk(const float4* __restrict__ in4,
                                          float4* __restrict__ out4, unsigned chunk) {
    unsigned m0 = chunk * 1024u + threadIdx.x;
    unsigned src[4]; float4 v[4];
    #pragma unroll
    for (int e = 0; e < 4; e++) {
        unsigned m = m0 + (unsigned)e * 256u;       // m in [0, 8*784*192)
        unsigned b = m / 150528u;                   // 784*192 per batch
        src[e] = m + (b + 1u) * ROWF4;              // skip row 0 of each batch
    }
    #pragma unroll
    for (int e = 0; e < 4; e++) v[e] = in4[src[e]];
    #pragma unroll
    for (int e = 0; e < 4; e++) out4[src[e]] = v[e];
}

// ---- radix top-84 select for one (b,c) --------------------------------------
__device__ void doSelect(SmemSel& sm, const float* __restrict__ x, int bc) {
    int t = threadIdx.x;
    unsigned lane = t & 31;
    int wid = t >> 5;
    const float* base = x + (size_t)bc * NTOK * NTOK + 1;   // x[b,c,0,1:]
    for (int s = t; s < S_; s += 256) {
        float v = base[s];
        sm.sc[s]  = v;
        sm.key[s] = f2u(v);
    }
    if (t == 0) { sm.prefix = 0u; sm.k = PATCH; }

    #pragma unroll
    for (int p = 0; p < 4; p++) {
        int shift = 24 - 8 * p;
        sm.hist[t] = 0;
        __syncthreads();
        unsigned pref = sm.prefix;
        int      k    = sm.k;
        for (int s = t; s < S_; s += 256) {
            unsigned kk = sm.key[s];
            bool cand = (p == 0) || (((kk ^ pref) >> (shift + 8)) == 0u);
            if (cand) atomicAdd(&sm.hist[(kk >> shift) & 255], 1);
        }
        __syncthreads();
        int v = sm.hist[t];
        int xsum = v;
        #pragma unroll
        for (int off = 1; off < 32; off <<= 1) {
            int y = __shfl_down_sync(0xFFFFFFFFu, xsum, off);
            if (lane + off < 32) xsum += y;
        }
        if (lane == 0) sm.wtot[wid] = xsum;
        __syncthreads();
        int addhi = 0;
        for (int ww = wid + 1; ww < 8; ww++) addhi += sm.wtot[ww];
        int suffix = xsum + addhi;
        int above  = suffix - v;
        if (suffix >= k && above < k) {        // exactly one thread matches
            sm.prefix = pref | ((unsigned)t << shift);
            sm.k      = k - above;
        }
    }
    __syncthreads();

    unsigned T  = sm.prefix;
    int     neq = sm.k;
    for (int s = t; s < S_; s += 256) {
        unsigned kk = sm.key[s];
        bool sel;
        if (kk > T) sel = true;
        else if (kk == T) {
            int eq = 0;
            for (int u = 0; u < s; u++) eq += (sm.key[u] == T);
            sel = eq < neq;
        } else sel = false;
        float v = sm.sc[s];
        g_amap[bc*S_ + s]    = sel ? v : 0.7f * v;
        g_selflag[bc*S_ + s] = sel ? 1 : 0;
    }
}

// ---- per-batch analytics (rank-1 GCN collapse) ------------------------------
__device__ void doKB(SmemKB& sm, const float* __restrict__ w1, int b) {
    int t = threadIdx.x;
    unsigned lane = t & 31;
    int wid = t >> 5;
    const int NT = 256;

    float part = 0.f;
    for (int s = t; s < S_; s += NT) {
        float smv = 0.f;
        #pragma unroll
        for (int c = 0; c < C_; c++) smv += g_amap[(b*C_ + c)*S_ + s];
        sm.binm[s] = smv;
        sm.pw[s]   = smv * (1.f/12.f);
        part += smv;
    }
    #pragma unroll
    for (int off = 16; off > 0; off >>= 1) part += __shfl_down_sync(0xFFFFFFFFu, part, off);
    if (lane == 0) sm.wsum[wid] = part;
    __syncthreads();
    if (t < 8) {
        float v = sm.wsum[t];
        #pragma unroll
        for (int off = 4; off > 0; off >>= 1) v += __shfl_down_sync(0xFFu, v, off);
        if (t == 0) sm.mean = v / (float)S_;
    }
    __syncthreads();
    float mean = sm.mean;
    for (int s = t; s < S_; s += NT) sm.binm[s] = (sm.binm[s] > mean) ? 1.f : 0.f;

    // anchor = argmax binm*pw (first index wins), u64 key, -0.0 canonicalized
    unsigned long long akey = 0ull;
    for (int s = t; s < S_; s += NT) {
        float v = sm.binm[s] * sm.pw[s];
        unsigned uv = __float_as_uint(v);
        if (uv == 0x80000000u) uv = 0u;
        unsigned fv = (uv & 0x80000000u) ? ~uv : (uv | 0x80000000u);
        unsigned long long k = ((unsigned long long)fv << 32) | (unsigned long long)(0xFFFFFFFFu - (unsigned)s);
        if (k > akey) akey = k;
    }
    #pragma unroll
    for (int off = 16; off > 0; off >>= 1) {
        unsigned long long o = __shfl_down_sync(0xFFFFFFFFu, akey, off);
        if (o > akey) akey = o;
    }
    if (lane == 0) sm.wkey[wid] = akey;
    __syncthreads();
    if (t < 8) {
        unsigned long long k = sm.wkey[t];
        #pragma unroll
        for (int off = 4; off > 0; off >>= 1) {
            unsigned long long o = __shfl_down_sync(0xFFu, k, off);
            if (o > k) k = o;
        }
        if (t == 0) {
            int a = (int)(0xFFFFFFFFu - (unsigned)(k & 0xFFFFFFFFull));
            sm.anchor = a;
            sm.panchor = sm.pw[a];
        }
    }
    __syncthreads();
    int anchor = sm.anchor;
    float ai = (float)(anchor / HH), aj = (float)(anchor % HH);

    float4 acc4 = make_float4(0.f, 0.f, 0.f, 0.f);
    for (int s = t; s < S_; s += NT) {
        float rx = ((float)(s / HH) - ai) / 28.0f;
        float ry = ((float)(s % HH) - aj) / 28.0f;
        float dist = sqrtf(rx*rx + ry*ry);
        float ang  = (atan2f(ry, rx) / (float)M_PI + 1.f) * 0.5f;
        float p = sm.pw[s];
        acc4.x += p * dist;
        acc4.y += p * ang;
        if (p > 0.f) acc4.z += p*p; else if (p < 0.f) acc4.w += p*p;
    }
    #pragma unroll
    for (int off = 16; off > 0; off >>= 1) {
        acc4.x += __shfl_down_sync(0xFFFFFFFFu, acc4.x, off);
        acc4.y += __shfl_down_sync(0xFFFFFFFFu, acc4.y, off);
        acc4.z += __shfl_down_sync(0xFFFFFFFFu, acc4.z, off);
        acc4.w += __shfl_down_sync(0xFFFFFFFFu, acc4.w, off);
    }
    if (lane == 0) sm.wq[wid] = acc4;
    __syncthreads();
    if (t < 8) {
        float4 a = sm.wq[t];
        #pragma unroll
        for (int off = 4; off > 0; off >>= 1) {
            a.x += __shfl_down_sync(0xFFu, a.x, off);
            a.y += __shfl_down_sync(0xFFu, a.y, off);
            a.z += __shfl_down_sync(0xFFu, a.z, off);
            a.w += __shfl_down_sync(0xFFu, a.w, off);
        }
        if (t == 0) sm.q = a;
    }
    __syncthreads();
    float Q0 = sm.q.x, Q1 = sm.q.y, AP = sm.q.z, AM = sm.q.w;
    float pa = sm.panchor;

    for (int k = t; k < GCNH; k += NT) {
        float v = Q0 * w1[k] + Q1 * w1[GCNH + k];
        float wv = (v > 0.f) ? v * AP : ((v < 0.f) ? v * AM : 0.f);
        g_wk[b*GCNH + k] = pa * wv;
    }

    for (int s = t; s < S_; s += NT) {
        int c = 0;
        #pragma unroll
        for (int ch = 0; ch < C_; ch++) c += g_selflag[(b*C_ + ch)*S_ + s];
        sm.cnt[s] = (float)c;
    }
    __syncthreads();
    for (int s = t; s < S_; s += NT) {
        int li = s / HH, lj = s % HH;
        float acc = 0.f;
        #pragma unroll
        for (int di = -1; di <= 1; di++) {
            #pragma unroll
            for (int dj = -1; dj <= 1; dj++) {
                int ni = li + di, nj = lj + dj;
                if (ni >= 0 && ni < HH && nj >= 0 && nj < HH) {
                    float kw = ((di == 0) ? 2.f : 1.f) * ((dj == 0) ? 2.f : 1.f);
                    acc += kw * sm.cnt[ni*HH + nj];
                }
            }
        }
        g_key[b*S_ + s] = (int)acc * 1024 + (1023 - s);
    }
}

// ---------------- the single fused kernel ----------------
__global__ void __launch_bounds__(256, 2)
kAll(const float* __restrict__ x, const float* __restrict__ w1,
     const float* __restrict__ w2, const float4* __restrict__ in4,
     float4* __restrict__ out4, unsigned sn) {
    __shared__ SmemAll sm;
    unsigned bid = blockIdx.x;
    unsigned NB  = gridDim.x;
    int t = threadIdx.x;

    // ===== Phase 1: radix selects + copy part 1 =====
    for (unsigned task = bid; task < 96u; task += NB) doSelect(sm.sel, x, (int)task);
    for (unsigned c = bid; c < CH_P1; c += NB) copyChunk(in4, out4, c);
    gridSync(NB);

    // ===== Phase 2: per-batch analytics + copy part 2 =====
    for (unsigned task = bid; task < 8u; task += NB) doKB(sm.kb, w1, (int)task);
    if (NB > 8u) {
        if (bid >= 8u)
            for (unsigned c = CH_P1 + (bid - 8u); c < NCHUNK; c += NB - 8u)
                copyChunk(in4, out4, c);
    } else {
        for (unsigned c = CH_P1 + bid; c < NCHUNK; c += NB)
            copyChunk(in4, out4, c);
    }
    gridSync(NB);

    // ===== Phase 3: matvec tiles (0..191) + rank (192..223) =====
    for (unsigned task = bid; task < 224u; task += NB) {
        __syncthreads();                           // smem reuse across tasks
        if (task < 192u) {
            int b    = (int)(task / 24u);
            int tile = (int)(task - (unsigned)b * 24u);
            for (int k = t; k < GCNH; k += 256) sm.mv.wk[k] = g_wk[b*GCNH + k];
            __syncthreads();
            int col = tile * 32 + (t & 31);
            int jq  = t >> 5;
            const float* w2p = w2 + col;
            float acc = 0.f;
            int j0 = jq * 64;
            #pragma unroll 8
            for (int j = 0; j < 64; j++) acc += sm.mv.wk[j0 + j] * w2p[(size_t)(j0 + j) * D_];
            sm.mv.partr[t] = acc;
            __syncthreads();
            if (t < 32) {
                float o = 0.f;
                #pragma unroll
                for (int q = 0; q < 8; q++) o += sm.mv.partr[t + q*32];
                int c = tile * 32 + t;
                g_struct[b*D_ + c] = (o > 0.f) ? o : 0.2f * o;
            }
        } else {
            unsigned idx = task - 192u;            // 0..31
            int b    = (int)(idx >> 2);
            int part = (int)(idx & 3u);
            for (int s = t; s < S_; s += 256) sm.rk.kk[s] = g_key[b*S_ + s];
            __syncthreads();
            if (t < 196) {
                int s = part * 196 + t;
                int ks = sm.rk.kk[s];
                int r = 0;
                #pragma unroll 8
                for (int u = 0; u < S_; u++) r += (sm.rk.kk[u] > ks);
                if (r < (int)sn) g_pidx[b*S_ + r] = s + 1;
            }
        }
    }
    gridSync(NB);

    // ===== Phase 4: row-0 add + gather =====
    unsigned ntail = 1536u + sn * 8u * ROWF4;
    for (unsigned i = bid * 256u + (unsigned)t; i < ntail; i += NB * 256u) {
        if (i < 1536u) {
            unsigned b  = i / ROWF4;
            unsigned k4 = i - b * ROWF4;
            float4 v = in4[b*BATF4 + k4];
            float4 st = ((const float4*)g_struct)[b*ROWF4 + k4];
            v.x += st.x; v.y += st.y; v.z += st.z; v.w += st.w;
            out4[b*BATF4 + k4] = v;
        } else {
            unsigned j  = i - 1536u;
            unsigned rr = j / ROWF4;               // b*sn + jj
            unsigned k4 = j - rr * ROWF4;
            unsigned b  = rr / sn;
            unsigned jj = rr - b * sn;
            unsigned row = (unsigned)g_pidx[b*S_ + jj];
            out4[NHS4 + j] = in4[(b*785u + row)*ROWF4 + k4];
        }
    }
}

// ---------------- launch ----------------
extern "C" void kernel_launch(void* const* d_in, const int* in_sizes, int n_in,
                              void* d_out, int out_size) {
    const float* hs = (const float*)d_in[0];
    const float* x  = (const float*)d_in[1];
    const float* w1 = (const float*)d_in[2];
    const float* w2 = (const float*)d_in[3];
    (void)in_sizes; (void)n_in;

    int sn = out_size / (B_ * D_) - NTOK;     // selected rows per batch
    if (sn < 1) sn = 1;
    if (sn > S_) sn = S_;

    int nsm = 0;
    if (cudaDeviceGetAttribute(&nsm, cudaDevAttrMultiProcessorCount, 0) != cudaSuccess || nsm <= 0)
        nsm = 64;                              // conservative fallback
    unsigned nblk = (unsigned)nsm * 2u;        // __launch_bounds__(256,2) guarantees residency

    kAll<<<nblk, 256>>>(x, w1, w2, (const float4*)hs, (float4*)d_out, (unsigned)sn);
}